// round 1
// baseline (speedup 1.0000x reference)
#include <cuda_runtime.h>
#include <math.h>

// Problem constants
#define BB   4
#define SS   2048
#define EE   1024
#define HHN  16
#define DKH  64
#define FFD  4096
#define MR   (BB*SS)   /* 8192 rows */

// ---------------------------------------------------------------------------
// Scratch (static __device__ arrays: allocation-free per harness rules)
// ---------------------------------------------------------------------------
__device__ float g_qkv[(size_t)MR * 3 * EE];   // 96 MB
__device__ float g_att[(size_t)MR * EE];       // 32 MB
__device__ float g_r1 [(size_t)MR * EE];       // 32 MB
__device__ float g_x1 [(size_t)MR * EE];       // 32 MB
__device__ float g_h  [(size_t)MR * FFD];      // 128 MB
__device__ float g_r2 [(size_t)MR * EE];       // 32 MB

// ---------------------------------------------------------------------------
// GEMM: C[M,N] = A[M,K] @ W[N,K]^T + bias (+ residual) (ReLU)
// 128x128 tile, BK=16, 256 threads, 8x8 per thread.
// All M,N,K here are multiples of the tile sizes -> no bounds checks.
// ---------------------------------------------------------------------------
template<bool RELU, bool RES>
__global__ __launch_bounds__(256, 2)
void gemm_tn(const float* __restrict__ A, const float* __restrict__ W,
             const float* __restrict__ bias, const float* __restrict__ res,
             float* __restrict__ C, int M, int N, int K)
{
    __shared__ float As[16][128];
    __shared__ float Bs[16][128];

    const int tid = threadIdx.x;
    const int bm  = blockIdx.y * 128;
    const int bn  = blockIdx.x * 128;
    const int tx  = tid & 15;          // N direction (8 cols each)
    const int ty  = tid >> 4;          // M direction (8 rows each)
    const int lrow = tid >> 1;         // 0..127 : tile row loaded by this thread
    const int lcol = (tid & 1) * 8;    // 0 or 8 : starting k within tile

    const float* Ag = A + (size_t)(bm + lrow) * K + lcol;
    const float* Wg = W + (size_t)(bn + lrow) * K + lcol;

    float acc[8][8];
#pragma unroll
    for (int i = 0; i < 8; i++)
#pragma unroll
        for (int j = 0; j < 8; j++) acc[i][j] = 0.f;

    for (int kt = 0; kt < K; kt += 16) {
        float4 a0 = *(const float4*)(Ag + kt);
        float4 a1 = *(const float4*)(Ag + kt + 4);
        float4 w0 = *(const float4*)(Wg + kt);
        float4 w1 = *(const float4*)(Wg + kt + 4);
        __syncthreads();
        As[lcol + 0][lrow] = a0.x; As[lcol + 1][lrow] = a0.y;
        As[lcol + 2][lrow] = a0.z; As[lcol + 3][lrow] = a0.w;
        As[lcol + 4][lrow] = a1.x; As[lcol + 5][lrow] = a1.y;
        As[lcol + 6][lrow] = a1.z; As[lcol + 7][lrow] = a1.w;
        Bs[lcol + 0][lrow] = w0.x; Bs[lcol + 1][lrow] = w0.y;
        Bs[lcol + 2][lrow] = w0.z; Bs[lcol + 3][lrow] = w0.w;
        Bs[lcol + 4][lrow] = w1.x; Bs[lcol + 5][lrow] = w1.y;
        Bs[lcol + 6][lrow] = w1.z; Bs[lcol + 7][lrow] = w1.w;
        __syncthreads();
#pragma unroll
        for (int k = 0; k < 16; k++) {
            float a[8], b[8];
            *(float4*)&a[0] = *(const float4*)&As[k][ty * 8];
            *(float4*)&a[4] = *(const float4*)&As[k][ty * 8 + 4];
            *(float4*)&b[0] = *(const float4*)&Bs[k][tx * 8];
            *(float4*)&b[4] = *(const float4*)&Bs[k][tx * 8 + 4];
#pragma unroll
            for (int i = 0; i < 8; i++)
#pragma unroll
                for (int j = 0; j < 8; j++)
                    acc[i][j] += a[i] * b[j];
        }
    }

    const int crow = bm + ty * 8;
    const int ccol = bn + tx * 8;
    float bv[8];
    *(float4*)&bv[0] = *(const float4*)(bias + ccol);
    *(float4*)&bv[4] = *(const float4*)(bias + ccol + 4);

#pragma unroll
    for (int i = 0; i < 8; i++) {
        float* cp = C + (size_t)(crow + i) * N + ccol;
        float o[8];
#pragma unroll
        for (int j = 0; j < 8; j++) o[j] = acc[i][j] + bv[j];
        if (RES) {
            const float* rp = res + (size_t)(crow + i) * N + ccol;
            float4 r0 = *(const float4*)rp;
            float4 r1 = *(const float4*)(rp + 4);
            o[0] += r0.x; o[1] += r0.y; o[2] += r0.z; o[3] += r0.w;
            o[4] += r1.x; o[5] += r1.y; o[6] += r1.z; o[7] += r1.w;
        }
        if (RELU) {
#pragma unroll
            for (int j = 0; j < 8; j++) o[j] = fmaxf(o[j], 0.f);
        }
        *(float4*)cp       = make_float4(o[0], o[1], o[2], o[3]);
        *(float4*)(cp + 4) = make_float4(o[4], o[5], o[6], o[7]);
    }
}

// ---------------------------------------------------------------------------
// Flash attention (fp32, online softmax).
// Block = (b, h, q-tile of 64). 256 threads = 8 warps; warp owns 8 query rows.
// Lane owns score/output columns {lane, lane+32} of 64.
// ---------------------------------------------------------------------------
#define ATTN_SMEM (4 * 64 * 65 * 4)

__global__ __launch_bounds__(256)
void attn_kernel(const float* __restrict__ qkv, float* __restrict__ out)
{
    extern __shared__ float sm[];
    float (*Qs)[65] = (float (*)[65])(sm);
    float (*Ks)[65] = (float (*)[65])(sm + 64 * 65);
    float (*Vs)[65] = (float (*)[65])(sm + 2 * 64 * 65);
    float (*Ps)[65] = (float (*)[65])(sm + 3 * 64 * 65);

    const int qt   = blockIdx.x;        // 0..31
    const int bh   = blockIdx.y;        // 0..63
    const int b    = bh >> 4;
    const int h    = bh & 15;
    const int tid  = threadIdx.x;
    const int lane = tid & 31;
    const int warp = tid >> 5;
    const int r0   = warp * 8;

    const float* qbase = qkv + (size_t)b * SS * (3 * EE);

    // Load Q tile [64 x 64]
#pragma unroll
    for (int i = 0; i < 4; i++) {
        int f = tid + 256 * i;
        int r = f >> 4;
        int d = (f & 15) * 4;
        float4 v = *(const float4*)(qbase + (size_t)(qt * 64 + r) * (3 * EE) + h * 64 + d);
        Qs[r][d] = v.x; Qs[r][d + 1] = v.y; Qs[r][d + 2] = v.z; Qs[r][d + 3] = v.w;
    }

    float m_r[8], l_r[8], oa[8], ob[8];
#pragma unroll
    for (int r = 0; r < 8; r++) { m_r[r] = -1e30f; l_r[r] = 0.f; oa[r] = 0.f; ob[r] = 0.f; }

    for (int kt = 0; kt < SS / 64; kt++) {
        __syncthreads();   // prev tile fully consumed (also covers Q on iter 0)
#pragma unroll
        for (int i = 0; i < 4; i++) {
            int f = tid + 256 * i;
            int r = f >> 4;
            int d = (f & 15) * 4;
            const float* krow = qbase + (size_t)(kt * 64 + r) * (3 * EE) + EE + h * 64;
            float4 kv = *(const float4*)(krow + d);
            float4 vv = *(const float4*)(krow + EE + d);
            Ks[r][d] = kv.x; Ks[r][d + 1] = kv.y; Ks[r][d + 2] = kv.z; Ks[r][d + 3] = kv.w;
            Vs[r][d] = vv.x; Vs[r][d + 1] = vv.y; Vs[r][d + 2] = vv.z; Vs[r][d + 3] = vv.w;
        }
        __syncthreads();

        // ---- scores: S = Q K^T * 0.125 ----
        float s[8][2];
#pragma unroll
        for (int rr = 0; rr < 8; rr += 4) {
            float a0[4], a1[4];
#pragma unroll
            for (int i = 0; i < 4; i++) { a0[i] = 0.f; a1[i] = 0.f; }
#pragma unroll 4
            for (int d = 0; d < 64; d++) {
                float k0 = Ks[lane][d];
                float k1 = Ks[lane + 32][d];
#pragma unroll
                for (int i = 0; i < 4; i++) {
                    float q = Qs[r0 + rr + i][d];
                    a0[i] += q * k0;
                    a1[i] += q * k1;
                }
            }
#pragma unroll
            for (int i = 0; i < 4; i++) {
                s[rr + i][0] = a0[i] * 0.125f;
                s[rr + i][1] = a1[i] * 0.125f;
            }
        }

        // ---- online softmax stats + write P ----
#pragma unroll
        for (int r = 0; r < 8; r++) {
            float mx = fmaxf(s[r][0], s[r][1]);
#pragma unroll
            for (int o = 16; o; o >>= 1) mx = fmaxf(mx, __shfl_xor_sync(0xffffffffu, mx, o));
            float mnew = fmaxf(m_r[r], mx);
            float p0 = __expf(s[r][0] - mnew);
            float p1 = __expf(s[r][1] - mnew);
            float rs = p0 + p1;
#pragma unroll
            for (int o = 16; o; o >>= 1) rs += __shfl_xor_sync(0xffffffffu, rs, o);
            float corr = __expf(m_r[r] - mnew);
            l_r[r] = l_r[r] * corr + rs;
            oa[r] *= corr;
            ob[r] *= corr;
            m_r[r] = mnew;
            Ps[r0 + r][lane]      = p0;
            Ps[r0 + r][lane + 32] = p1;
        }
        __syncwarp();

        // ---- O += P @ V ----
#pragma unroll 4
        for (int c = 0; c < 64; c++) {
            float v0 = Vs[c][lane];
            float v1 = Vs[c][lane + 32];
#pragma unroll
            for (int r = 0; r < 8; r++) {
                float p = Ps[r0 + r][c];
                oa[r] += p * v0;
                ob[r] += p * v1;
            }
        }
    }

    // epilogue: normalize and write concat-head output
#pragma unroll
    for (int r = 0; r < 8; r++) {
        float inv = 1.f / l_r[r];
        size_t row = (size_t)b * SS + qt * 64 + r0 + r;
        out[row * EE + h * 64 + lane]      = oa[r] * inv;
        out[row * EE + h * 64 + lane + 32] = ob[r] * inv;
    }
}

// ---------------------------------------------------------------------------
// LayerNorm over last dim (E=1024), one block per row, 256 threads x float4.
// ---------------------------------------------------------------------------
__global__ __launch_bounds__(256)
void ln_kernel(const float* __restrict__ r, const float* __restrict__ g,
               const float* __restrict__ be, float* __restrict__ out)
{
    const int row = blockIdx.x;
    const int tid = threadIdx.x;
    const int lane = tid & 31, warp = tid >> 5;

    float4 v = ((const float4*)(r + (size_t)row * EE))[tid];
    float s  = v.x + v.y + v.z + v.w;
    float sq = v.x * v.x + v.y * v.y + v.z * v.z + v.w * v.w;
#pragma unroll
    for (int o = 16; o; o >>= 1) {
        s  += __shfl_xor_sync(0xffffffffu, s,  o);
        sq += __shfl_xor_sync(0xffffffffu, sq, o);
    }
    __shared__ float ss[8], ssq[8];
    if (lane == 0) { ss[warp] = s; ssq[warp] = sq; }
    __syncthreads();
    float ts = 0.f, tq = 0.f;
#pragma unroll
    for (int i = 0; i < 8; i++) { ts += ss[i]; tq += ssq[i]; }
    float mu   = ts * (1.0f / EE);
    float var  = tq * (1.0f / EE) - mu * mu;
    float rstd = rsqrtf(var + 1e-5f);

    float4 gv = ((const float4*)g)[tid];
    float4 bv = ((const float4*)be)[tid];
    float4 o;
    o.x = (v.x - mu) * rstd * gv.x + bv.x;
    o.y = (v.y - mu) * rstd * gv.y + bv.y;
    o.z = (v.z - mu) * rstd * gv.z + bv.z;
    o.w = (v.w - mu) * rstd * gv.w + bv.w;
    ((float4*)(out + (size_t)row * EE))[tid] = o;
}

// ---------------------------------------------------------------------------
// Launch
// ---------------------------------------------------------------------------
extern "C" void kernel_launch(void* const* d_in, const int* in_sizes, int n_in,
                              void* d_out, int out_size)
{
    (void)in_sizes; (void)n_in; (void)out_size;
    const float* x     = (const float*)d_in[0];
    const float* w_qkv = (const float*)d_in[1];
    const float* b_qkv = (const float*)d_in[2];
    const float* w_out = (const float*)d_in[3];
    const float* b_out = (const float*)d_in[4];
    const float* w1    = (const float*)d_in[5];
    const float* b1    = (const float*)d_in[6];
    const float* w2    = (const float*)d_in[7];
    const float* b2    = (const float*)d_in[8];
    const float* g1    = (const float*)d_in[9];
    const float* be1   = (const float*)d_in[10];
    const float* g2    = (const float*)d_in[11];
    const float* be2   = (const float*)d_in[12];
    float* out = (float*)d_out;

    float *p_qkv, *p_att, *p_r1, *p_x1, *p_h, *p_r2;
    cudaGetSymbolAddress((void**)&p_qkv, g_qkv);
    cudaGetSymbolAddress((void**)&p_att, g_att);
    cudaGetSymbolAddress((void**)&p_r1,  g_r1);
    cudaGetSymbolAddress((void**)&p_x1,  g_x1);
    cudaGetSymbolAddress((void**)&p_h,   g_h);
    cudaGetSymbolAddress((void**)&p_r2,  g_r2);

    cudaFuncSetAttribute(attn_kernel, cudaFuncAttributeMaxDynamicSharedMemorySize, ATTN_SMEM);

    // 1) QKV projection: [8192,1024] @ [3072,1024]^T -> [8192,3072]
    gemm_tn<false, false><<<dim3(3 * EE / 128, MR / 128), 256>>>(
        x, w_qkv, b_qkv, nullptr, p_qkv, MR, 3 * EE, EE);

    // 2) attention -> [8192,1024]
    attn_kernel<<<dim3(SS / 64, BB * HHN), 256, ATTN_SMEM>>>(p_qkv, p_att);

    // 3) out-proj + residual(x) -> r1
    gemm_tn<false, true><<<dim3(EE / 128, MR / 128), 256>>>(
        p_att, w_out, b_out, x, p_r1, MR, EE, EE);

    // 4) LN1 -> x1
    ln_kernel<<<MR, 256>>>(p_r1, g1, be1, p_x1);

    // 5) FFN up + ReLU -> h
    gemm_tn<true, false><<<dim3(FFD / 128, MR / 128), 256>>>(
        p_x1, w1, b1, nullptr, p_h, MR, FFD, EE);

    // 6) FFN down + residual(x1) -> r2
    gemm_tn<false, true><<<dim3(EE / 128, MR / 128), 256>>>(
        p_h, w2, b2, p_x1, p_r2, MR, EE, FFD);

    // 7) LN2 -> out
    ln_kernel<<<MR, 256>>>(p_r2, g2, be2, out);
}

// round 3
// speedup vs baseline: 1.7550x; 1.7550x over previous
#include <cuda_runtime.h>
#include <cuda_bf16.h>
#include <cstdint>
#include <math.h>

// Problem constants
#define BB   4
#define SS   2048
#define EE   1024
#define HHN  16
#define DKH  64
#define FFD  4096
#define MR   (BB*SS)   /* 8192 rows */

// ---------------------------------------------------------------------------
// Scratch (static __device__ arrays: allocation-free per harness rules)
// ---------------------------------------------------------------------------
__device__ float g_qkv[(size_t)MR * 3 * EE];   // 96 MB
__device__ float g_att[(size_t)MR * EE];       // 32 MB
__device__ float g_r1 [(size_t)MR * EE];       // 32 MB
__device__ float g_x1 [(size_t)MR * EE];       // 32 MB
__device__ float g_h  [(size_t)MR * FFD];      // 128 MB
__device__ float g_r2 [(size_t)MR * EE];       // 32 MB

// ---------------------------------------------------------------------------
// Helpers
// ---------------------------------------------------------------------------
__device__ __forceinline__ uint32_t smem_u32(const void* p) {
    uint32_t a;
    asm("{ .reg .u64 t; cvta.to.shared.u64 t, %1; cvt.u32.u64 %0, t; }"
        : "=r"(a) : "l"(p));
    return a;
}

__device__ __forceinline__ void mma16816(float* c, const uint32_t* a, const uint32_t* b) {
    asm volatile(
        "mma.sync.aligned.m16n8k16.row.col.f32.bf16.bf16.f32 "
        "{%0,%1,%2,%3}, {%4,%5,%6,%7}, {%8,%9}, {%0,%1,%2,%3};"
        : "+f"(c[0]), "+f"(c[1]), "+f"(c[2]), "+f"(c[3])
        : "r"(a[0]), "r"(a[1]), "r"(a[2]), "r"(a[3]), "r"(b[0]), "r"(b[1]));
}

__device__ __forceinline__ void ldsm4(uint32_t* r, uint32_t addr) {
    asm volatile("ldmatrix.sync.aligned.m8n8.x4.shared.b16 {%0,%1,%2,%3}, [%4];"
        : "=r"(r[0]), "=r"(r[1]), "=r"(r[2]), "=r"(r[3]) : "r"(addr));
}

// ---------------------------------------------------------------------------
// GEMM via mma.sync bf16 3-pass split: C[M,N] = A[M,K] @ W[N,K]^T (+bias,res,relu)
// CTA tile 128x128, BK=32, 256 thr (8 warps, 2M x 4N), double-buffered smem.
// Smem tiles [128][32] bf16, row stride 80B (conflict-free ldmatrix).
// ---------------------------------------------------------------------------
#define SBYTE 80
#define TILE_A_HI 0
#define TILE_A_LO 10240
#define TILE_B_HI 20480
#define TILE_B_LO 30720
#define STAGE     40960
#define GSM_TOTAL (2 * STAGE)

__device__ __forceinline__ void cvt_store8(char* hi, char* lo, uint32_t boff, float4 v) {
    uint32_t h0, h1, l0, l1;
    asm("cvt.rn.bf16x2.f32 %0,%1,%2;" : "=r"(h0) : "f"(v.y), "f"(v.x));
    asm("cvt.rn.bf16x2.f32 %0,%1,%2;" : "=r"(h1) : "f"(v.w), "f"(v.z));
    float rx = v.x - __uint_as_float(h0 << 16);
    float ry = v.y - __uint_as_float(h0 & 0xFFFF0000u);
    float rz = v.z - __uint_as_float(h1 << 16);
    float rw = v.w - __uint_as_float(h1 & 0xFFFF0000u);
    asm("cvt.rn.bf16x2.f32 %0,%1,%2;" : "=r"(l0) : "f"(ry), "f"(rx));
    asm("cvt.rn.bf16x2.f32 %0,%1,%2;" : "=r"(l1) : "f"(rw), "f"(rz));
    *(uint2*)(hi + boff) = make_uint2(h0, h1);
    *(uint2*)(lo + boff) = make_uint2(l0, l1);
}

template<bool RELU, bool RES>
__global__ __launch_bounds__(256, 1)
void gemm_mma(const float* __restrict__ A, const float* __restrict__ W,
              const float* __restrict__ bias, const float* __restrict__ res,
              float* __restrict__ C, int N, int K)
{
    extern __shared__ char sm[];
    const int tid = threadIdx.x, lane = tid & 31, wid = tid >> 5;
    const int wm = wid & 1;        // 0..1 : M half (64 rows)
    const int wn = wid >> 1;       // 0..3 : N quarter (32 cols)
    const int bm = blockIdx.y * 128, bn = blockIdx.x * 128;
    const uint32_t sbase = smem_u32(sm);

    // ldmatrix per-lane byte offsets within a tile
    const uint32_t a_off = (uint32_t)(wm * 64 + (lane & 15)) * SBYTE + ((lane >> 4) * 16);
    const uint32_t b_off = (uint32_t)(wn * 32 + (lane & 7) + ((lane >> 4) << 3)) * SBYTE
                         + (((lane >> 3) & 1) * 16);

    // global loader mapping: thread covers rows r0 + 32*i, fixed float4 column c4
    const int c4 = tid & 7, r0 = tid >> 3;
    const float* Ap = A + (size_t)(bm + r0) * K + c4 * 4;
    const float* Wp = W + (size_t)(bn + r0) * K + c4 * 4;
    const uint32_t st_off = (uint32_t)r0 * SBYTE + c4 * 8;

    float acc[4][4][4];
#pragma unroll
    for (int mt = 0; mt < 4; mt++)
#pragma unroll
        for (int nt = 0; nt < 4; nt++)
#pragma unroll
            for (int j = 0; j < 4; j++) acc[mt][nt][j] = 0.f;

    float4 va[4], vb[4];
#pragma unroll
    for (int i = 0; i < 4; i++) {
        va[i] = *(const float4*)(Ap + (size_t)(32 * i) * K);
        vb[i] = *(const float4*)(Wp + (size_t)(32 * i) * K);
    }
#pragma unroll
    for (int i = 0; i < 4; i++) {
        uint32_t o = st_off + i * 32 * SBYTE;
        cvt_store8(sm + TILE_A_HI, sm + TILE_A_LO, o, va[i]);
        cvt_store8(sm + TILE_B_HI, sm + TILE_B_LO, o, vb[i]);
    }
    __syncthreads();

    const int KT = K >> 5;
    for (int kt = 0; kt < KT; kt++) {
        if (kt + 1 < KT) {
#pragma unroll
            for (int i = 0; i < 4; i++) {
                va[i] = *(const float4*)(Ap + (size_t)(32 * i) * K + (kt + 1) * 32);
                vb[i] = *(const float4*)(Wp + (size_t)(32 * i) * K + (kt + 1) * 32);
            }
        }
        const uint32_t base = sbase + (kt & 1) * STAGE;
#pragma unroll
        for (int ks = 0; ks < 2; ks++) {
            uint32_t ah[4][4], al[4][4], bh[2][4], bl[2][4];
#pragma unroll
            for (int t = 0; t < 4; t++) {
                ldsm4(ah[t], base + TILE_A_HI + a_off + t * (16 * SBYTE) + ks * 32);
                ldsm4(al[t], base + TILE_A_LO + a_off + t * (16 * SBYTE) + ks * 32);
            }
#pragma unroll
            for (int i = 0; i < 2; i++) {
                ldsm4(bh[i], base + TILE_B_HI + b_off + i * (16 * SBYTE) + ks * 32);
                ldsm4(bl[i], base + TILE_B_LO + b_off + i * (16 * SBYTE) + ks * 32);
            }
#pragma unroll
            for (int mt = 0; mt < 4; mt++)
#pragma unroll
                for (int nt = 0; nt < 4; nt++) {
                    const uint32_t* bph = &bh[nt >> 1][(nt & 1) * 2];
                    const uint32_t* bpl = &bl[nt >> 1][(nt & 1) * 2];
                    mma16816(acc[mt][nt], al[mt], bph);   // lo*hi
                    mma16816(acc[mt][nt], ah[mt], bpl);   // hi*lo
                    mma16816(acc[mt][nt], ah[mt], bph);   // hi*hi
                }
        }
        if (kt + 1 < KT) {
            char* nb = sm + ((kt + 1) & 1) * STAGE;
#pragma unroll
            for (int i = 0; i < 4; i++) {
                uint32_t o = st_off + i * 32 * SBYTE;
                cvt_store8(nb + TILE_A_HI, nb + TILE_A_LO, o, va[i]);
                cvt_store8(nb + TILE_B_HI, nb + TILE_B_LO, o, vb[i]);
            }
        }
        __syncthreads();
    }

    // Epilogue: D fragment (m16n8): d0,d1 @ (row=lane>>2, col=(lane&3)*2), d2,d3 @ row+8
    const int erow = bm + wm * 64 + (lane >> 2);
    const int ecol = bn + wn * 32 + (lane & 3) * 2;
#pragma unroll
    for (int mt = 0; mt < 4; mt++)
#pragma unroll
        for (int nt = 0; nt < 4; nt++) {
            const int col = ecol + nt * 8;
            float2 bv = *(const float2*)(bias + col);
#pragma unroll
            for (int h = 0; h < 2; h++) {
                const int row = erow + mt * 16 + h * 8;
                float o0 = acc[mt][nt][h * 2 + 0] + bv.x;
                float o1 = acc[mt][nt][h * 2 + 1] + bv.y;
                if (RES) {
                    float2 rv = *(const float2*)(res + (size_t)row * N + col);
                    o0 += rv.x; o1 += rv.y;
                }
                if (RELU) { o0 = fmaxf(o0, 0.f); o1 = fmaxf(o1, 0.f); }
                *(float2*)(C + (size_t)row * N + col) = make_float2(o0, o1);
            }
        }
}

// ---------------------------------------------------------------------------
// Flash attention (fp32, online softmax) — unchanged
// ---------------------------------------------------------------------------
#define ATTN_SMEM (4 * 64 * 65 * 4)

__global__ __launch_bounds__(256)
void attn_kernel(const float* __restrict__ qkv, float* __restrict__ out)
{
    extern __shared__ float smf[];
    float (*Qs)[65] = (float (*)[65])(smf);
    float (*Ks)[65] = (float (*)[65])(smf + 64 * 65);
    float (*Vs)[65] = (float (*)[65])(smf + 2 * 64 * 65);
    float (*Ps)[65] = (float (*)[65])(smf + 3 * 64 * 65);

    const int qt   = blockIdx.x;
    const int bh   = blockIdx.y;
    const int b    = bh >> 4;
    const int h    = bh & 15;
    const int tid  = threadIdx.x;
    const int lane = tid & 31;
    const int warp = tid >> 5;
    const int r0   = warp * 8;

    const float* qbase = qkv + (size_t)b * SS * (3 * EE);

#pragma unroll
    for (int i = 0; i < 4; i++) {
        int f = tid + 256 * i;
        int r = f >> 4;
        int d = (f & 15) * 4;
        float4 v = *(const float4*)(qbase + (size_t)(qt * 64 + r) * (3 * EE) + h * 64 + d);
        Qs[r][d] = v.x; Qs[r][d + 1] = v.y; Qs[r][d + 2] = v.z; Qs[r][d + 3] = v.w;
    }

    float m_r[8], l_r[8], oa[8], ob[8];
#pragma unroll
    for (int r = 0; r < 8; r++) { m_r[r] = -1e30f; l_r[r] = 0.f; oa[r] = 0.f; ob[r] = 0.f; }

    for (int kt = 0; kt < SS / 64; kt++) {
        __syncthreads();
#pragma unroll
        for (int i = 0; i < 4; i++) {
            int f = tid + 256 * i;
            int r = f >> 4;
            int d = (f & 15) * 4;
            const float* krow = qbase + (size_t)(kt * 64 + r) * (3 * EE) + EE + h * 64;
            float4 kv = *(const float4*)(krow + d);
            float4 vv = *(const float4*)(krow + EE + d);
            Ks[r][d] = kv.x; Ks[r][d + 1] = kv.y; Ks[r][d + 2] = kv.z; Ks[r][d + 3] = kv.w;
            Vs[r][d] = vv.x; Vs[r][d + 1] = vv.y; Vs[r][d + 2] = vv.z; Vs[r][d + 3] = vv.w;
        }
        __syncthreads();

        float s[8][2];
#pragma unroll
        for (int rr = 0; rr < 8; rr += 4) {
            float a0[4], a1[4];
#pragma unroll
            for (int i = 0; i < 4; i++) { a0[i] = 0.f; a1[i] = 0.f; }
#pragma unroll 4
            for (int d = 0; d < 64; d++) {
                float k0 = Ks[lane][d];
                float k1 = Ks[lane + 32][d];
#pragma unroll
                for (int i = 0; i < 4; i++) {
                    float q = Qs[r0 + rr + i][d];
                    a0[i] += q * k0;
                    a1[i] += q * k1;
                }
            }
#pragma unroll
            for (int i = 0; i < 4; i++) {
                s[rr + i][0] = a0[i] * 0.125f;
                s[rr + i][1] = a1[i] * 0.125f;
            }
        }

#pragma unroll
        for (int r = 0; r < 8; r++) {
            float mx = fmaxf(s[r][0], s[r][1]);
#pragma unroll
            for (int o = 16; o; o >>= 1) mx = fmaxf(mx, __shfl_xor_sync(0xffffffffu, mx, o));
            float mnew = fmaxf(m_r[r], mx);
            float p0 = __expf(s[r][0] - mnew);
            float p1 = __expf(s[r][1] - mnew);
            float rs = p0 + p1;
#pragma unroll
            for (int o = 16; o; o >>= 1) rs += __shfl_xor_sync(0xffffffffu, rs, o);
            float corr = __expf(m_r[r] - mnew);
            l_r[r] = l_r[r] * corr + rs;
            oa[r] *= corr;
            ob[r] *= corr;
            m_r[r] = mnew;
            Ps[r0 + r][lane]      = p0;
            Ps[r0 + r][lane + 32] = p1;
        }
        __syncwarp();

#pragma unroll 4
        for (int c = 0; c < 64; c++) {
            float v0 = Vs[c][lane];
            float v1 = Vs[c][lane + 32];
#pragma unroll
            for (int r = 0; r < 8; r++) {
                float p = Ps[r0 + r][c];
                oa[r] += p * v0;
                ob[r] += p * v1;
            }
        }
    }

#pragma unroll
    for (int r = 0; r < 8; r++) {
        float inv = 1.f / l_r[r];
        size_t row = (size_t)b * SS + qt * 64 + r0 + r;
        out[row * EE + h * 64 + lane]      = oa[r] * inv;
        out[row * EE + h * 64 + lane + 32] = ob[r] * inv;
    }
}

// ---------------------------------------------------------------------------
// LayerNorm (unchanged)
// ---------------------------------------------------------------------------
__global__ __launch_bounds__(256)
void ln_kernel(const float* __restrict__ r, const float* __restrict__ g,
               const float* __restrict__ be, float* __restrict__ out)
{
    const int row = blockIdx.x;
    const int tid = threadIdx.x;
    const int lane = tid & 31, warp = tid >> 5;

    float4 v = ((const float4*)(r + (size_t)row * EE))[tid];
    float s  = v.x + v.y + v.z + v.w;
    float sq = v.x * v.x + v.y * v.y + v.z * v.z + v.w * v.w;
#pragma unroll
    for (int o = 16; o; o >>= 1) {
        s  += __shfl_xor_sync(0xffffffffu, s,  o);
        sq += __shfl_xor_sync(0xffffffffu, sq, o);
    }
    __shared__ float ss[8], ssq[8];
    if (lane == 0) { ss[warp] = s; ssq[warp] = sq; }
    __syncthreads();
    float ts = 0.f, tq = 0.f;
#pragma unroll
    for (int i = 0; i < 8; i++) { ts += ss[i]; tq += ssq[i]; }
    float mu   = ts * (1.0f / EE);
    float var  = tq * (1.0f / EE) - mu * mu;
    float rstd = rsqrtf(var + 1e-5f);

    float4 gv = ((const float4*)g)[tid];
    float4 bv = ((const float4*)be)[tid];
    float4 o;
    o.x = (v.x - mu) * rstd * gv.x + bv.x;
    o.y = (v.y - mu) * rstd * gv.y + bv.y;
    o.z = (v.z - mu) * rstd * gv.z + bv.z;
    o.w = (v.w - mu) * rstd * gv.w + bv.w;
    ((float4*)(out + (size_t)row * EE))[tid] = o;
}

// ---------------------------------------------------------------------------
// Launch
// ---------------------------------------------------------------------------
extern "C" void kernel_launch(void* const* d_in, const int* in_sizes, int n_in,
                              void* d_out, int out_size)
{
    (void)in_sizes; (void)n_in; (void)out_size;
    const float* x     = (const float*)d_in[0];
    const float* w_qkv = (const float*)d_in[1];
    const float* b_qkv = (const float*)d_in[2];
    const float* w_out = (const float*)d_in[3];
    const float* b_out = (const float*)d_in[4];
    const float* w1    = (const float*)d_in[5];
    const float* b1    = (const float*)d_in[6];
    const float* w2    = (const float*)d_in[7];
    const float* b2    = (const float*)d_in[8];
    const float* g1    = (const float*)d_in[9];
    const float* be1   = (const float*)d_in[10];
    const float* g2    = (const float*)d_in[11];
    const float* be2   = (const float*)d_in[12];
    float* out = (float*)d_out;

    float *p_qkv, *p_att, *p_r1, *p_x1, *p_h, *p_r2;
    cudaGetSymbolAddress((void**)&p_qkv, g_qkv);
    cudaGetSymbolAddress((void**)&p_att, g_att);
    cudaGetSymbolAddress((void**)&p_r1,  g_r1);
    cudaGetSymbolAddress((void**)&p_x1,  g_x1);
    cudaGetSymbolAddress((void**)&p_h,   g_h);
    cudaGetSymbolAddress((void**)&p_r2,  g_r2);

    cudaFuncSetAttribute(attn_kernel, cudaFuncAttributeMaxDynamicSharedMemorySize, ATTN_SMEM);
    cudaFuncSetAttribute(gemm_mma<false, false>, cudaFuncAttributeMaxDynamicSharedMemorySize, GSM_TOTAL);
    cudaFuncSetAttribute(gemm_mma<false, true>,  cudaFuncAttributeMaxDynamicSharedMemorySize, GSM_TOTAL);
    cudaFuncSetAttribute(gemm_mma<true, false>,  cudaFuncAttributeMaxDynamicSharedMemorySize, GSM_TOTAL);

    // 1) QKV projection: [8192,1024] @ [3072,1024]^T -> [8192,3072]
    gemm_mma<false, false><<<dim3(3 * EE / 128, MR / 128), 256, GSM_TOTAL>>>(
        x, w_qkv, b_qkv, nullptr, p_qkv, 3 * EE, EE);

    // 2) attention -> [8192,1024]
    attn_kernel<<<dim3(SS / 64, BB * HHN), 256, ATTN_SMEM>>>(p_qkv, p_att);

    // 3) out-proj + residual(x) -> r1
    gemm_mma<false, true><<<dim3(EE / 128, MR / 128), 256, GSM_TOTAL>>>(
        p_att, w_out, b_out, x, p_r1, EE, EE);

    // 4) LN1 -> x1
    ln_kernel<<<MR, 256>>>(p_r1, g1, be1, p_x1);

    // 5) FFN up + ReLU -> h
    gemm_mma<true, false><<<dim3(FFD / 128, MR / 128), 256, GSM_TOTAL>>>(
        p_x1, w1, b1, nullptr, p_h, FFD, EE);

    // 6) FFN down + residual(x1) -> r2
    gemm_mma<false, true><<<dim3(EE / 128, MR / 128), 256, GSM_TOTAL>>>(
        p_h, w2, b2, p_x1, p_r2, EE, FFD);

    // 7) LN2 -> out
    ln_kernel<<<MR, 256>>>(p_r2, g2, be2, out);
}

// round 5
// speedup vs baseline: 3.1678x; 1.8050x over previous
#include <cuda_runtime.h>
#include <cuda_bf16.h>
#include <cstdint>
#include <math.h>

// Problem constants
#define BB   4
#define SS   2048
#define EE   1024
#define HHN  16
#define DKH  64
#define FFD  4096
#define MR   (BB*SS)   /* 8192 rows */

// ---------------------------------------------------------------------------
// Scratch
// ---------------------------------------------------------------------------
__device__ float g_qkv[(size_t)MR * 3 * EE];   // 96 MB
__device__ float g_att[(size_t)MR * EE];       // 32 MB
__device__ float g_r1 [(size_t)MR * EE];       // 32 MB
__device__ float g_x1 [(size_t)MR * EE];       // 32 MB
__device__ float g_h  [(size_t)MR * FFD];      // 128 MB
__device__ float g_r2 [(size_t)MR * EE];       // 32 MB

// ---------------------------------------------------------------------------
// Helpers
// ---------------------------------------------------------------------------
__device__ __forceinline__ uint32_t smem_u32(const void* p) {
    uint32_t a;
    asm("{ .reg .u64 t; cvta.to.shared.u64 t, %1; cvt.u32.u64 %0, t; }"
        : "=r"(a) : "l"(p));
    return a;
}

__device__ __forceinline__ void mma16816(float* c, const uint32_t* a, const uint32_t* b) {
    asm volatile(
        "mma.sync.aligned.m16n8k16.row.col.f32.bf16.bf16.f32 "
        "{%0,%1,%2,%3}, {%4,%5,%6,%7}, {%8,%9}, {%0,%1,%2,%3};"
        : "+f"(c[0]), "+f"(c[1]), "+f"(c[2]), "+f"(c[3])
        : "r"(a[0]), "r"(a[1]), "r"(a[2]), "r"(a[3]), "r"(b[0]), "r"(b[1]));
}

__device__ __forceinline__ void ldsm4(uint32_t* r, uint32_t addr) {
    asm volatile("ldmatrix.sync.aligned.m8n8.x4.shared.b16 {%0,%1,%2,%3}, [%4];"
        : "=r"(r[0]), "=r"(r[1]), "=r"(r[2]), "=r"(r[3]) : "r"(addr));
}

__device__ __forceinline__ void ldsm4t(uint32_t* r, uint32_t addr) {
    asm volatile("ldmatrix.sync.aligned.m8n8.x4.trans.shared.b16 {%0,%1,%2,%3}, [%4];"
        : "=r"(r[0]), "=r"(r[1]), "=r"(r[2]), "=r"(r[3]) : "r"(addr));
}

__device__ __forceinline__ void cvt_store8(char* hi, char* lo, uint32_t boff, float4 v) {
    uint32_t h0, h1, l0, l1;
    asm("cvt.rn.bf16x2.f32 %0,%1,%2;" : "=r"(h0) : "f"(v.y), "f"(v.x));
    asm("cvt.rn.bf16x2.f32 %0,%1,%2;" : "=r"(h1) : "f"(v.w), "f"(v.z));
    float rx = v.x - __uint_as_float(h0 << 16);
    float ry = v.y - __uint_as_float(h0 & 0xFFFF0000u);
    float rz = v.z - __uint_as_float(h1 << 16);
    float rw = v.w - __uint_as_float(h1 & 0xFFFF0000u);
    asm("cvt.rn.bf16x2.f32 %0,%1,%2;" : "=r"(l0) : "f"(ry), "f"(rx));
    asm("cvt.rn.bf16x2.f32 %0,%1,%2;" : "=r"(l1) : "f"(rw), "f"(rz));
    *(uint2*)(hi + boff) = make_uint2(h0, h1);
    *(uint2*)(lo + boff) = make_uint2(l0, l1);
}

// ---------------------------------------------------------------------------
// GEMM via mma.sync bf16 3-pass split: C[M,N] = A[M,K] @ W[N,K]^T (+bias,res,relu)
// CTA tile 128x128, BK=32, 256 thr (8 warps, 2M x 4N), double-buffered smem.
// ---------------------------------------------------------------------------
#define SBYTE 80
#define TILE_A_HI 0
#define TILE_A_LO 10240
#define TILE_B_HI 20480
#define TILE_B_LO 30720
#define STAGE     40960
#define GSM_TOTAL (2 * STAGE)

template<bool RELU, bool RES>
__global__ __launch_bounds__(256, 1)
void gemm_mma(const float* __restrict__ A, const float* __restrict__ W,
              const float* __restrict__ bias, const float* __restrict__ res,
              float* __restrict__ C, int N, int K)
{
    extern __shared__ char sm[];
    const int tid = threadIdx.x, lane = tid & 31, wid = tid >> 5;
    const int wm = wid & 1;
    const int wn = wid >> 1;
    const int bm = blockIdx.y * 128, bn = blockIdx.x * 128;
    const uint32_t sbase = smem_u32(sm);

    const uint32_t a_off = (uint32_t)(wm * 64 + (lane & 15)) * SBYTE + ((lane >> 4) * 16);
    const uint32_t b_off = (uint32_t)(wn * 32 + (lane & 7) + ((lane >> 4) << 3)) * SBYTE
                         + (((lane >> 3) & 1) * 16);

    const int c4 = tid & 7, r0 = tid >> 3;
    const float* Ap = A + (size_t)(bm + r0) * K + c4 * 4;
    const float* Wp = W + (size_t)(bn + r0) * K + c4 * 4;
    const uint32_t st_off = (uint32_t)r0 * SBYTE + c4 * 8;

    float acc[4][4][4];
#pragma unroll
    for (int mt = 0; mt < 4; mt++)
#pragma unroll
        for (int nt = 0; nt < 4; nt++)
#pragma unroll
            for (int j = 0; j < 4; j++) acc[mt][nt][j] = 0.f;

    float4 va[4], vb[4];
#pragma unroll
    for (int i = 0; i < 4; i++) {
        va[i] = *(const float4*)(Ap + (size_t)(32 * i) * K);
        vb[i] = *(const float4*)(Wp + (size_t)(32 * i) * K);
    }
#pragma unroll
    for (int i = 0; i < 4; i++) {
        uint32_t o = st_off + i * 32 * SBYTE;
        cvt_store8(sm + TILE_A_HI, sm + TILE_A_LO, o, va[i]);
        cvt_store8(sm + TILE_B_HI, sm + TILE_B_LO, o, vb[i]);
    }
    __syncthreads();

    const int KT = K >> 5;
    for (int kt = 0; kt < KT; kt++) {
        if (kt + 1 < KT) {
#pragma unroll
            for (int i = 0; i < 4; i++) {
                va[i] = *(const float4*)(Ap + (size_t)(32 * i) * K + (kt + 1) * 32);
                vb[i] = *(const float4*)(Wp + (size_t)(32 * i) * K + (kt + 1) * 32);
            }
        }
        const uint32_t base = sbase + (kt & 1) * STAGE;
#pragma unroll
        for (int ks = 0; ks < 2; ks++) {
            uint32_t ah[4][4], al[4][4], bh[2][4], bl[2][4];
#pragma unroll
            for (int t = 0; t < 4; t++) {
                ldsm4(ah[t], base + TILE_A_HI + a_off + t * (16 * SBYTE) + ks * 32);
                ldsm4(al[t], base + TILE_A_LO + a_off + t * (16 * SBYTE) + ks * 32);
            }
#pragma unroll
            for (int i = 0; i < 2; i++) {
                ldsm4(bh[i], base + TILE_B_HI + b_off + i * (16 * SBYTE) + ks * 32);
                ldsm4(bl[i], base + TILE_B_LO + b_off + i * (16 * SBYTE) + ks * 32);
            }
#pragma unroll
            for (int mt = 0; mt < 4; mt++)
#pragma unroll
                for (int nt = 0; nt < 4; nt++) {
                    const uint32_t* bph = &bh[nt >> 1][(nt & 1) * 2];
                    const uint32_t* bpl = &bl[nt >> 1][(nt & 1) * 2];
                    mma16816(acc[mt][nt], al[mt], bph);
                    mma16816(acc[mt][nt], ah[mt], bpl);
                    mma16816(acc[mt][nt], ah[mt], bph);
                }
        }
        if (kt + 1 < KT) {
            char* nb = sm + ((kt + 1) & 1) * STAGE;
#pragma unroll
            for (int i = 0; i < 4; i++) {
                uint32_t o = st_off + i * 32 * SBYTE;
                cvt_store8(nb + TILE_A_HI, nb + TILE_A_LO, o, va[i]);
                cvt_store8(nb + TILE_B_HI, nb + TILE_B_LO, o, vb[i]);
            }
        }
        __syncthreads();
    }

    const int erow = bm + wm * 64 + (lane >> 2);
    const int ecol = bn + wn * 32 + (lane & 3) * 2;
#pragma unroll
    for (int mt = 0; mt < 4; mt++)
#pragma unroll
        for (int nt = 0; nt < 4; nt++) {
            const int col = ecol + nt * 8;
            float2 bv = *(const float2*)(bias + col);
#pragma unroll
            for (int h = 0; h < 2; h++) {
                const int row = erow + mt * 16 + h * 8;
                float o0 = acc[mt][nt][h * 2 + 0] + bv.x;
                float o1 = acc[mt][nt][h * 2 + 1] + bv.y;
                if (RES) {
                    float2 rv = *(const float2*)(res + (size_t)row * N + col);
                    o0 += rv.x; o1 += rv.y;
                }
                if (RELU) { o0 = fmaxf(o0, 0.f); o1 = fmaxf(o1, 0.f); }
                *(float2*)(C + (size_t)row * N + col) = make_float2(o0, o1);
            }
        }
}

// ---------------------------------------------------------------------------
// Flash attention via mma.sync (bf16 3-pass split, FA2 layout)
// CTA = (b, h, 128-query block); 8 warps x 16 query rows; 64-key tiles.
// ---------------------------------------------------------------------------
#define ASTR   144
#define AQ_HI  0
#define AQ_LO  (128 * ASTR)
#define AK_HI  (2 * 128 * ASTR)
#define AK_LO  (AK_HI + 64 * ASTR)
#define AV_HI  (AK_LO + 64 * ASTR)
#define AV_LO  (AV_HI + 64 * ASTR)
#define ATT_SMEM (AV_LO + 64 * ASTR)   /* 73728 */

__global__ __launch_bounds__(256, 1)
void attn_mma(const float* __restrict__ qkv, float* __restrict__ out)
{
    extern __shared__ char sm[];
    const uint32_t sb = smem_u32(sm);
    const int tid = threadIdx.x, lane = tid & 31, w = tid >> 5;
    const int qt = blockIdx.x;           // 0..15
    const int bh = blockIdx.y;           // 0..63
    const int b = bh >> 4, h = bh & 15;

    const float* base = qkv + (size_t)b * SS * (3 * EE);

    // ---- load Q tile [128 x 64], scaled by 1/8 (exact), split hi/lo ----
    {
        const int c4 = tid & 15, r0 = tid >> 4;   // 16 f4-cols, 16 row groups
#pragma unroll
        for (int i = 0; i < 8; i++) {
            int r = r0 + 16 * i;
            float4 v = *(const float4*)(base + (size_t)(qt * 128 + r) * (3 * EE) + h * 64 + c4 * 4);
            v.x *= 0.125f; v.y *= 0.125f; v.z *= 0.125f; v.w *= 0.125f;
            cvt_store8(sm + AQ_HI, sm + AQ_LO, (uint32_t)r * ASTR + c4 * 8, v);
        }
    }

    // ---- KV loader mapping: c4 fixed, rows kr0 + 16*i ----
    const int c4 = tid & 15, kr0 = tid >> 4;
    const float* kbase = base + EE + h * 64 + c4 * 4;
    const float* vbase = base + 2 * EE + h * 64 + c4 * 4;

    float4 kreg[4], vreg[4];
#pragma unroll
    for (int i = 0; i < 4; i++) {
        kreg[i] = *(const float4*)(kbase + (size_t)(kr0 + 16 * i) * (3 * EE));
        vreg[i] = *(const float4*)(vbase + (size_t)(kr0 + 16 * i) * (3 * EE));
    }
#pragma unroll
    for (int i = 0; i < 4; i++) {
        uint32_t o = (uint32_t)(kr0 + 16 * i) * ASTR + c4 * 8;
        cvt_store8(sm + AK_HI, sm + AK_LO, o, kreg[i]);
        cvt_store8(sm + AV_HI, sm + AV_LO, o, vreg[i]);
    }
    __syncthreads();

    // ldmatrix offsets
    const uint32_t a_off = (uint32_t)(w * 16 + (lane & 15)) * ASTR + ((lane >> 4) * 16);
    const uint32_t b_off = (uint32_t)((lane & 7) + ((lane >> 4) << 3)) * ASTR
                         + (((lane >> 3) & 1) * 16);
    const uint32_t v_off = (uint32_t)(lane & 15) * ASTR + ((lane >> 4) * 16);

    float mA = -1e30f, mB = -1e30f, lA = 0.f, lB = 0.f;
    float O[8][4];
#pragma unroll
    for (int j = 0; j < 8; j++)
#pragma unroll
        for (int k = 0; k < 4; k++) O[j][k] = 0.f;

    const int NT = SS / 64;   // 32 key tiles
    for (int kt = 0; kt < NT; kt++) {
        const bool more = (kt + 1 < NT);
        if (more) {
#pragma unroll
            for (int i = 0; i < 4; i++) {
                kreg[i] = *(const float4*)(kbase + (size_t)((kt + 1) * 64 + kr0 + 16 * i) * (3 * EE));
                vreg[i] = *(const float4*)(vbase + (size_t)((kt + 1) * 64 + kr0 + 16 * i) * (3 * EE));
            }
        }

        // ---- S = Q K^T (scaled) ----
        float S[8][4];
#pragma unroll
        for (int j = 0; j < 8; j++)
#pragma unroll
            for (int k = 0; k < 4; k++) S[j][k] = 0.f;

#pragma unroll
        for (int kd = 0; kd < 4; kd++) {
            uint32_t ah[4], al[4];
            ldsm4(ah, sb + AQ_HI + a_off + kd * 32);
            ldsm4(al, sb + AQ_LO + a_off + kd * 32);
#pragma unroll
            for (int i = 0; i < 4; i++) {
                uint32_t bh4[4], bl4[4];
                ldsm4(bh4, sb + AK_HI + b_off + i * (16 * ASTR) + kd * 32);
                ldsm4(bl4, sb + AK_LO + b_off + i * (16 * ASTR) + kd * 32);
                mma16816(S[2 * i],     al, &bh4[0]);
                mma16816(S[2 * i],     ah, &bl4[0]);
                mma16816(S[2 * i],     ah, &bh4[0]);
                mma16816(S[2 * i + 1], al, &bh4[2]);
                mma16816(S[2 * i + 1], ah, &bl4[2]);
                mma16816(S[2 * i + 1], ah, &bh4[2]);
            }
        }

        // ---- online softmax (rows A = lane>>2, B = +8) ----
        float txA = -1e30f, txB = -1e30f;
#pragma unroll
        for (int j = 0; j < 8; j++) {
            txA = fmaxf(txA, fmaxf(S[j][0], S[j][1]));
            txB = fmaxf(txB, fmaxf(S[j][2], S[j][3]));
        }
        txA = fmaxf(txA, __shfl_xor_sync(0xffffffffu, txA, 1));
        txA = fmaxf(txA, __shfl_xor_sync(0xffffffffu, txA, 2));
        txB = fmaxf(txB, __shfl_xor_sync(0xffffffffu, txB, 1));
        txB = fmaxf(txB, __shfl_xor_sync(0xffffffffu, txB, 2));
        const float mnA = fmaxf(mA, txA), mnB = fmaxf(mB, txB);
        const float cA = __expf(mA - mnA), cB = __expf(mB - mnB);

        float sA = 0.f, sB = 0.f;
#pragma unroll
        for (int j = 0; j < 8; j++) {
            S[j][0] = __expf(S[j][0] - mnA);
            S[j][1] = __expf(S[j][1] - mnA);
            S[j][2] = __expf(S[j][2] - mnB);
            S[j][3] = __expf(S[j][3] - mnB);
            sA += S[j][0] + S[j][1];
            sB += S[j][2] + S[j][3];
        }
        sA += __shfl_xor_sync(0xffffffffu, sA, 1);
        sA += __shfl_xor_sync(0xffffffffu, sA, 2);
        sB += __shfl_xor_sync(0xffffffffu, sB, 1);
        sB += __shfl_xor_sync(0xffffffffu, sB, 2);
        lA = lA * cA + sA;  mA = mnA;
        lB = lB * cB + sB;  mB = mnB;
#pragma unroll
        for (int j = 0; j < 8; j++) {
            O[j][0] *= cA; O[j][1] *= cA;
            O[j][2] *= cB; O[j][3] *= cB;
        }

        // ---- O += P V (P split hi/lo in registers, V via ldmatrix.trans) ----
#pragma unroll
        for (int kk = 0; kk < 4; kk++) {
            uint32_t ph[4], pl[4];
#pragma unroll
            for (int u = 0; u < 2; u++) {           // u: S tile 2kk+u
                const float* sp = S[2 * kk + u];
#pragma unroll
                for (int hf = 0; hf < 2; hf++) {     // hf: d0d1 vs d2d3
                    uint32_t hh;
                    asm("cvt.rn.bf16x2.f32 %0,%1,%2;" : "=r"(hh)
                        : "f"(sp[2 * hf + 1]), "f"(sp[2 * hf]));
                    float r0f = sp[2 * hf]     - __uint_as_float(hh << 16);
                    float r1f = sp[2 * hf + 1] - __uint_as_float(hh & 0xFFFF0000u);
                    uint32_t ll;
                    asm("cvt.rn.bf16x2.f32 %0,%1,%2;" : "=r"(ll) : "f"(r1f), "f"(r0f));
                    ph[2 * u + hf] = hh;
                    pl[2 * u + hf] = ll;
                }
            }
#pragma unroll
            for (int nn = 0; nn < 2; nn++) {
#pragma unroll
                for (int q = 0; q < 2; q++) {
                    const int dimc = nn * 2 + q;     // 0..3 : 16-dim chunk
                    uint32_t vh[4], vl[4];
                    ldsm4t(vh, sb + AV_HI + v_off + (uint32_t)(kk * 16) * ASTR + dimc * 32);
                    ldsm4t(vl, sb + AV_LO + v_off + (uint32_t)(kk * 16) * ASTR + dimc * 32);
                    mma16816(O[2 * dimc],     pl, &vh[0]);
                    mma16816(O[2 * dimc],     ph, &vl[0]);
                    mma16816(O[2 * dimc],     ph, &vh[0]);
                    mma16816(O[2 * dimc + 1], pl, &vh[2]);
                    mma16816(O[2 * dimc + 1], ph, &vl[2]);
                    mma16816(O[2 * dimc + 1], ph, &vh[2]);
                }
            }
        }

        __syncthreads();
        if (more) {
#pragma unroll
            for (int i = 0; i < 4; i++) {
                uint32_t o = (uint32_t)(kr0 + 16 * i) * ASTR + c4 * 8;
                cvt_store8(sm + AK_HI, sm + AK_LO, o, kreg[i]);
                cvt_store8(sm + AV_HI, sm + AV_LO, o, vreg[i]);
            }
            __syncthreads();
        }
    }

    // ---- epilogue ----
    const float invA = 1.f / lA, invB = 1.f / lB;
    const size_t rowA = (size_t)b * SS + qt * 128 + w * 16 + (lane >> 2);
    float* oA = out + rowA * EE + h * 64 + (lane & 3) * 2;
    float* oB = oA + (size_t)8 * EE;
#pragma unroll
    for (int j = 0; j < 8; j++) {
        *(float2*)(oA + j * 8) = make_float2(O[j][0] * invA, O[j][1] * invA);
        *(float2*)(oB + j * 8) = make_float2(O[j][2] * invB, O[j][3] * invB);
    }
}

// ---------------------------------------------------------------------------
// LayerNorm (unchanged)
// ---------------------------------------------------------------------------
__global__ __launch_bounds__(256)
void ln_kernel(const float* __restrict__ r, const float* __restrict__ g,
               const float* __restrict__ be, float* __restrict__ out)
{
    const int row = blockIdx.x;
    const int tid = threadIdx.x;
    const int lane = tid & 31, warp = tid >> 5;

    float4 v = ((const float4*)(r + (size_t)row * EE))[tid];
    float s  = v.x + v.y + v.z + v.w;
    float sq = v.x * v.x + v.y * v.y + v.z * v.z + v.w * v.w;
#pragma unroll
    for (int o = 16; o; o >>= 1) {
        s  += __shfl_xor_sync(0xffffffffu, s,  o);
        sq += __shfl_xor_sync(0xffffffffu, sq, o);
    }
    __shared__ float ss[8], ssq[8];
    if (lane == 0) { ss[warp] = s; ssq[warp] = sq; }
    __syncthreads();
    float ts = 0.f, tq = 0.f;
#pragma unroll
    for (int i = 0; i < 8; i++) { ts += ss[i]; tq += ssq[i]; }
    float mu   = ts * (1.0f / EE);
    float var  = tq * (1.0f / EE) - mu * mu;
    float rstd = rsqrtf(var + 1e-5f);

    float4 gv = ((const float4*)g)[tid];
    float4 bv = ((const float4*)be)[tid];
    float4 o;
    o.x = (v.x - mu) * rstd * gv.x + bv.x;
    o.y = (v.y - mu) * rstd * gv.y + bv.y;
    o.z = (v.z - mu) * rstd * gv.z + bv.z;
    o.w = (v.w - mu) * rstd * gv.w + bv.w;
    ((float4*)(out + (size_t)row * EE))[tid] = o;
}

// ---------------------------------------------------------------------------
// Launch
// ---------------------------------------------------------------------------
extern "C" void kernel_launch(void* const* d_in, const int* in_sizes, int n_in,
                              void* d_out, int out_size)
{
    (void)in_sizes; (void)n_in; (void)out_size;
    const float* x     = (const float*)d_in[0];
    const float* w_qkv = (const float*)d_in[1];
    const float* b_qkv = (const float*)d_in[2];
    const float* w_out = (const float*)d_in[3];
    const float* b_out = (const float*)d_in[4];
    const float* w1    = (const float*)d_in[5];
    const float* b1    = (const float*)d_in[6];
    const float* w2    = (const float*)d_in[7];
    const float* b2    = (const float*)d_in[8];
    const float* g1    = (const float*)d_in[9];
    const float* be1   = (const float*)d_in[10];
    const float* g2    = (const float*)d_in[11];
    const float* be2   = (const float*)d_in[12];
    float* out = (float*)d_out;

    float *p_qkv, *p_att, *p_r1, *p_x1, *p_h, *p_r2;
    cudaGetSymbolAddress((void**)&p_qkv, g_qkv);
    cudaGetSymbolAddress((void**)&p_att, g_att);
    cudaGetSymbolAddress((void**)&p_r1,  g_r1);
    cudaGetSymbolAddress((void**)&p_x1,  g_x1);
    cudaGetSymbolAddress((void**)&p_h,   g_h);
    cudaGetSymbolAddress((void**)&p_r2,  g_r2);

    cudaFuncSetAttribute(attn_mma, cudaFuncAttributeMaxDynamicSharedMemorySize, ATT_SMEM);
    cudaFuncSetAttribute(gemm_mma<false, false>, cudaFuncAttributeMaxDynamicSharedMemorySize, GSM_TOTAL);
    cudaFuncSetAttribute(gemm_mma<false, true>,  cudaFuncAttributeMaxDynamicSharedMemorySize, GSM_TOTAL);
    cudaFuncSetAttribute(gemm_mma<true, false>,  cudaFuncAttributeMaxDynamicSharedMemorySize, GSM_TOTAL);

    // 1) QKV projection
    gemm_mma<false, false><<<dim3(3 * EE / 128, MR / 128), 256, GSM_TOTAL>>>(
        x, w_qkv, b_qkv, nullptr, p_qkv, 3 * EE, EE);

    // 2) attention (tensor-core flash attention)
    attn_mma<<<dim3(SS / 128, BB * HHN), 256, ATT_SMEM>>>(p_qkv, p_att);

    // 3) out-proj + residual(x)
    gemm_mma<false, true><<<dim3(EE / 128, MR / 128), 256, GSM_TOTAL>>>(
        p_att, w_out, b_out, x, p_r1, EE, EE);

    // 4) LN1
    ln_kernel<<<MR, 256>>>(p_r1, g1, be1, p_x1);

    // 5) FFN up + ReLU
    gemm_mma<true, false><<<dim3(FFD / 128, MR / 128), 256, GSM_TOTAL>>>(
        p_x1, w1, b1, nullptr, p_h, FFD, EE);

    // 6) FFN down + residual(x1)
    gemm_mma<false, true><<<dim3(EE / 128, MR / 128), 256, GSM_TOTAL>>>(
        p_h, w2, b2, p_x1, p_r2, EE, FFD);

    // 7) LN2
    ln_kernel<<<MR, 256>>>(p_r2, g2, be2, out);
}